// round 1
// baseline (speedup 1.0000x reference)
#include <cuda_runtime.h>

#define NN 100000
#define NE 600000
#define D  128

#define BM 128
#define BN 128
#define BK 16
#define TM 8
#define TN 8

// Scratch for h = x @ W_l  (51.2 MB)
__device__ float g_h[(size_t)NN * D];

// C = A @ B ; y==0: B=W_l -> g_h ; y==1: B=W_r -> out (+ bias_l + bias_r)
__global__ void __launch_bounds__(256) gemm_kernel(
    const float* __restrict__ A,
    const float* __restrict__ Wl,
    const float* __restrict__ Wr,
    const float* __restrict__ bl,
    const float* __restrict__ br,
    float* __restrict__ out)
{
    __shared__ float As[BK][BM];
    __shared__ float Bs[BK][BN];

    const int m0 = blockIdx.x * BM;
    const bool right = (blockIdx.y == 1);
    const float* __restrict__ B = right ? Wr : Wl;

    const int tid  = threadIdx.x;
    const int tcol = tid % (BN / TN);   // 0..15
    const int trow = tid / (BN / TN);   // 0..15

    float acc[TM][TN];
    #pragma unroll
    for (int i = 0; i < TM; i++)
        #pragma unroll
        for (int j = 0; j < TN; j++)
            acc[i][j] = 0.f;

    for (int kt = 0; kt < D; kt += BK) {
        // Load A tile 128x16 (512 float4 slots, 2 per thread), store transposed
        #pragma unroll
        for (int i = 0; i < 2; i++) {
            int slot = tid + i * 256;
            int r  = slot >> 2;          // 0..127
            int c4 = (slot & 3) * 4;     // 0,4,8,12
            int gr = m0 + r;
            float4 v = make_float4(0.f, 0.f, 0.f, 0.f);
            if (gr < NN)
                v = *(const float4*)&A[(size_t)gr * D + kt + c4];
            As[c4 + 0][r] = v.x;
            As[c4 + 1][r] = v.y;
            As[c4 + 2][r] = v.z;
            As[c4 + 3][r] = v.w;
        }
        // Load B tile 16x128 (512 float4 slots, 2 per thread)
        #pragma unroll
        for (int i = 0; i < 2; i++) {
            int slot = tid + i * 256;
            int r  = slot >> 5;          // 0..15
            int c4 = (slot & 31) * 4;    // 0..124
            *(float4*)&Bs[r][c4] = *(const float4*)&B[(size_t)(kt + r) * D + c4];
        }
        __syncthreads();

        #pragma unroll
        for (int k = 0; k < BK; k++) {
            float ra[TM], rb[TN];
            #pragma unroll
            for (int i = 0; i < TM; i++) ra[i] = As[k][trow * TM + i];
            #pragma unroll
            for (int j = 0; j < TN; j++) rb[j] = Bs[k][tcol * TN + j];
            #pragma unroll
            for (int i = 0; i < TM; i++)
                #pragma unroll
                for (int j = 0; j < TN; j++)
                    acc[i][j] += ra[i] * rb[j];
        }
        __syncthreads();
    }

    // Write back
    #pragma unroll
    for (int i = 0; i < TM; i++) {
        int gr = m0 + trow * TM + i;
        if (gr >= NN) continue;
        #pragma unroll
        for (int j = 0; j < TN; j += 4) {
            int gc = tcol * TN + j;
            float4 v = make_float4(acc[i][j], acc[i][j + 1], acc[i][j + 2], acc[i][j + 3]);
            if (right) {
                v.x += bl[gc + 0] + br[gc + 0];
                v.y += bl[gc + 1] + br[gc + 1];
                v.z += bl[gc + 2] + br[gc + 2];
                v.w += bl[gc + 3] + br[gc + 3];
                *(float4*)&out[(size_t)gr * D + gc] = v;
            } else {
                *(float4*)&g_h[(size_t)gr * D + gc] = v;
            }
        }
    }
}

// One warp per edge: out[dst] += w * h[src]  (vector f32 reduction, no return)
__global__ void __launch_bounds__(256) edge_kernel(
    const int* __restrict__ esrc,
    const int* __restrict__ edst,
    const float* __restrict__ ew,
    float* __restrict__ out)
{
    int e = blockIdx.x * 8 + (threadIdx.x >> 5);
    if (e >= NE) return;
    int lane = threadIdx.x & 31;

    int s = __ldg(&esrc[e]);
    int d = __ldg(&edst[e]);
    float wt = __ldg(&ew[e]);

    float4 v = *(const float4*)&g_h[(size_t)s * D + lane * 4];
    v.x *= wt; v.y *= wt; v.z *= wt; v.w *= wt;

    float* op = &out[(size_t)d * D + lane * 4];
    asm volatile("red.global.add.v4.f32 [%0], {%1, %2, %3, %4};"
                 :: "l"(op), "f"(v.x), "f"(v.y), "f"(v.z), "f"(v.w)
                 : "memory");
}

extern "C" void kernel_launch(void* const* d_in, const int* in_sizes, int n_in,
                              void* d_out, int out_size)
{
    const float* x    = (const float*)d_in[0];
    const int*   esrc = (const int*)  d_in[1];
    const int*   edst = (const int*)  d_in[2];
    const float* ew   = (const float*)d_in[3];
    const float* wl   = (const float*)d_in[4];
    const float* bl   = (const float*)d_in[5];
    const float* wr   = (const float*)d_in[6];
    const float* br   = (const float*)d_in[7];
    float* out = (float*)d_out;

    dim3 grid((NN + BM - 1) / BM, 2);
    gemm_kernel<<<grid, 256>>>(x, wl, wr, bl, br, out);
    edge_kernel<<<(NE + 7) / 8, 256>>>(esrc, edst, ew, out);
}

// round 3
// speedup vs baseline: 1.2056x; 1.2056x over previous
#include <cuda_runtime.h>
#include <mma.h>
#include <cstdint>

using namespace nvcuda;

#define NN 100000
#define NE 600000
#define D  128

// GEMM tiling
#define BM 128
#define BN 256          // combined: cols 0-127 -> W_l (g_h), 128-255 -> W_r (out)
#define BK 32
#define NWARP 16        // 512 threads; warp tile 32x64
#define LDA 36          // A smem leading dim (pad)
#define LDB 264         // B smem leading dim (pad)

// smem byte offsets
#define SM_AS   0
#define SM_BS   (SM_AS + BM * LDA * 4)            // 18432
#define SM_BIAS (SM_BS + BK * LDB * 4)            // 18432 + 33792 = 52224
#define SM_TOT  (SM_BIAS + 16 * LDB * 4)          // + 16896 = 69120

__device__ float g_h[(size_t)NN * D];   // h = x @ W_l

__global__ void __launch_bounds__(512, 1) gemm_wmma_kernel(
    const float* __restrict__ x,
    const float* __restrict__ wl,
    const float* __restrict__ bl,
    const float* __restrict__ wr,
    const float* __restrict__ br,
    float* __restrict__ out)
{
    extern __shared__ char smem[];
    float* As = (float*)(smem + SM_AS);      // [BM][LDA]
    float* Bs = (float*)(smem + SM_BS);      // [BK][LDB]
    float* Bias = (float*)(smem + SM_BIAS);  // [16][LDB]

    const int tid = threadIdx.x;
    const int wid = tid >> 5;
    const int warp_m = wid & 3;     // 0..3 -> 32-row group
    const int warp_n = wid >> 2;    // 0..3 -> 64-col group
    const int m0 = blockIdx.x * BM;

    // Build bias replica tile: 16 identical rows; left half 0, right half bl+br
    for (int s = tid; s < 16 * LDB; s += 512) {
        int c = s % LDB;
        float v = 0.f;
        if (c >= 128 && c < 256) v = bl[c - 128] + br[c - 128];
        Bias[s] = v;
    }
    __syncthreads();

    // Accumulators initialized from bias tile
    wmma::fragment<wmma::accumulator, 16, 16, 8, float> acc[2][4];
    #pragma unroll
    for (int i = 0; i < 2; i++)
        #pragma unroll
        for (int j = 0; j < 4; j++) {
            int c0 = warp_n * 64 + j * 16;
            wmma::load_matrix_sync(acc[i][j], &Bias[c0], LDB, wmma::mem_row_major);
        }

    for (int kt = 0; kt < D; kt += BK) {
        // Load A chunk [128 x 32] (1024 float4 slots, 2/thread)
        #pragma unroll
        for (int it = 0; it < 2; it++) {
            int s = tid + it * 512;         // 0..1023
            int row = s >> 3;               // 0..127
            int c4  = (s & 7) * 4;          // 0..28
            float4 v = make_float4(0.f, 0.f, 0.f, 0.f);
            int gr = m0 + row;
            if (gr < NN) v = *(const float4*)&x[(size_t)gr * D + kt + c4];
            *(float4*)&As[row * LDA + c4] = v;
        }
        // Load B chunk [32 x 256] from wl|wr (2048 float4 slots, 4/thread)
        #pragma unroll
        for (int it = 0; it < 4; it++) {
            int s = tid + it * 512;         // 0..2047
            int row = s >> 6;               // 0..31
            int c4  = (s & 63) * 4;         // 0..252
            int k = kt + row;
            float4 v;
            if (c4 < 128) v = *(const float4*)&wl[(size_t)k * D + c4];
            else          v = *(const float4*)&wr[(size_t)k * D + (c4 - 128)];
            *(float4*)&Bs[row * LDB + c4] = v;
        }
        __syncthreads();

        #pragma unroll
        for (int kf = 0; kf < BK / 8; kf++) {
            wmma::fragment<wmma::matrix_a, 16, 16, 8, wmma::precision::tf32, wmma::row_major> af[2];
            #pragma unroll
            for (int i = 0; i < 2; i++) {
                wmma::load_matrix_sync(af[i], &As[(warp_m * 32 + i * 16) * LDA + kf * 8], LDA);
                #pragma unroll
                for (int e = 0; e < af[i].num_elements; e++)
                    af[i].x[e] = wmma::__float_to_tf32(af[i].x[e]);
            }
            #pragma unroll
            for (int j = 0; j < 4; j++) {
                wmma::fragment<wmma::matrix_b, 16, 16, 8, wmma::precision::tf32, wmma::row_major> bf;
                wmma::load_matrix_sync(bf, &Bs[kf * 8 * LDB + warp_n * 64 + j * 16], LDB);
                #pragma unroll
                for (int e = 0; e < bf.num_elements; e++)
                    bf.x[e] = wmma::__float_to_tf32(bf.x[e]);
                #pragma unroll
                for (int i = 0; i < 2; i++)
                    wmma::mma_sync(acc[i][j], af[i], bf, acc[i][j]);
            }
        }
        __syncthreads();
    }

    // Epilogue: direct fragment stores to global (NN % 16 == 0 -> no partial tiles)
    #pragma unroll
    for (int i = 0; i < 2; i++) {
        int row0 = m0 + warp_m * 32 + i * 16;
        if (row0 >= NN) continue;
        #pragma unroll
        for (int j = 0; j < 4; j++) {
            int col0 = warp_n * 64 + j * 16;
            if (col0 < 128)
                wmma::store_matrix_sync(&g_h[(size_t)row0 * D + col0], acc[i][j], D,
                                        wmma::mem_row_major);
            else
                wmma::store_matrix_sync(&out[(size_t)row0 * D + (col0 - 128)], acc[i][j], D,
                                        wmma::mem_row_major);
        }
    }
}

// One warp per edge: out[dst] += w * h[src]  (vector f32 reduction, no return)
__global__ void __launch_bounds__(256) edge_kernel(
    const int* __restrict__ esrc,
    const int* __restrict__ edst,
    const float* __restrict__ ew,
    float* __restrict__ out)
{
    int e = blockIdx.x * 8 + (threadIdx.x >> 5);
    if (e >= NE) return;
    int lane = threadIdx.x & 31;

    int s = __ldg(&esrc[e]);
    int d = __ldg(&edst[e]);
    float wt = __ldg(&ew[e]);

    float4 v = *(const float4*)&g_h[(size_t)s * D + lane * 4];
    v.x *= wt; v.y *= wt; v.z *= wt; v.w *= wt;

    float* op = &out[(size_t)d * D + lane * 4];
    asm volatile("red.global.add.v4.f32 [%0], {%1, %2, %3, %4};"
                 :: "l"(op), "f"(v.x), "f"(v.y), "f"(v.z), "f"(v.w)
                 : "memory");
}

extern "C" void kernel_launch(void* const* d_in, const int* in_sizes, int n_in,
                              void* d_out, int out_size)
{
    const float* x    = (const float*)d_in[0];
    const int*   esrc = (const int*)  d_in[1];
    const int*   edst = (const int*)  d_in[2];
    const float* ew   = (const float*)d_in[3];
    const float* wl   = (const float*)d_in[4];
    const float* bl   = (const float*)d_in[5];
    const float* wr   = (const float*)d_in[6];
    const float* br   = (const float*)d_in[7];
    float* out = (float*)d_out;

    static bool attr_set = false;
    if (!attr_set) {
        cudaFuncSetAttribute(gemm_wmma_kernel,
                             cudaFuncAttributeMaxDynamicSharedMemorySize, SM_TOT);
        attr_set = true;
    }

    gemm_wmma_kernel<<<(NN + BM - 1) / BM, 512, SM_TOT>>>(x, wl, bl, wr, br, out);
    edge_kernel<<<(NE + 7) / 8, 256>>>(esrc, edst, ew, out);
}

// round 4
// speedup vs baseline: 1.4242x; 1.1813x over previous
#include <cuda_runtime.h>
#include <mma.h>
#include <cstdint>

using namespace nvcuda;

#define NN 100000
#define NE 600000
#define D  128
#define CAP 64          // bucket capacity per node (max degree ~Poisson(6), P(>40) ~ 1e-24)

// ---------------- device scratch ----------------
__device__ int   g_cnt[NN];
__device__ uint2 g_bucket[(size_t)NN * CAP];   // (src, weight_bits)
__device__ float g_agg[(size_t)NN * D];        // segment_sum(w * x[src])

// ---------------- phase 0: zero counters ----------------
__global__ void __launch_bounds__(256) zero_kernel() {
    int i = blockIdx.x * 256 + threadIdx.x;
    if (i < NN) g_cnt[i] = 0;
}

// ---------------- phase 1: scatter edges into buckets ----------------
__global__ void __launch_bounds__(256) scatter_kernel(
    const int* __restrict__ esrc,
    const int* __restrict__ edst,
    const float* __restrict__ ew)
{
    int e = blockIdx.x * 256 + threadIdx.x;
    if (e >= NE) return;
    int s = __ldg(&esrc[e]);
    int d = __ldg(&edst[e]);
    float w = __ldg(&ew[e]);
    int pos = atomicAdd(&g_cnt[d], 1);
    g_bucket[(size_t)d * CAP + pos] = make_uint2((unsigned)s, __float_as_uint(w));
}

// ---------------- phase 2: gather aggregate (warp per node, no atomics) ----------------
__global__ void __launch_bounds__(256) gather_kernel(const float* __restrict__ x)
{
    int n = blockIdx.x * 8 + (threadIdx.x >> 5);
    if (n >= NN) return;
    int lane = threadIdx.x & 31;

    int deg = g_cnt[n];
    float4 acc = make_float4(0.f, 0.f, 0.f, 0.f);
    const uint2* bk = &g_bucket[(size_t)n * CAP];
    for (int i = 0; i < deg; i++) {
        uint2 ent = __ldg(&bk[i]);
        float w = __uint_as_float(ent.y);
        float4 v = *(const float4*)&x[(size_t)ent.x * D + lane * 4];
        acc.x += w * v.x; acc.y += w * v.y; acc.z += w * v.z; acc.w += w * v.w;
    }
    *(float4*)&g_agg[(size_t)n * D + lane * 4] = acc;
}

// ---------------- phase 3: fused GEMM  out = [agg|x] @ [Wl;Wr] + (bl+br) ----------------
#define BM 128
#define BK 32
#define LDA 36
#define LDB 136

__global__ void __launch_bounds__(256, 1) gemm_kernel(
    const float* __restrict__ x,
    const float* __restrict__ wl,
    const float* __restrict__ bl,
    const float* __restrict__ wr,
    const float* __restrict__ br,
    float* __restrict__ out)
{
    __shared__ float As[BM][LDA];     // 18432 B
    __shared__ float Bs[BK][LDB];     // 17408 B
    __shared__ float Bias[16][LDB];   //  8704 B  (total 44544 < 48K)

    const int tid = threadIdx.x;
    const int wid = tid >> 5;
    const int warp_m = wid & 3;       // 0..3 -> 32-row group
    const int warp_n = wid >> 2;      // 0..1 -> 64-col group
    const int m0 = blockIdx.x * BM;

    // bias replica tile (16 identical rows of bl+br)
    for (int s = tid; s < 16 * LDB; s += 256) {
        int c = s % LDB;
        Bias[0][s] = (c < 128) ? (bl[c] + br[c]) : 0.f;
    }
    __syncthreads();

    wmma::fragment<wmma::accumulator, 16, 16, 8, float> acc[2][4];
    #pragma unroll
    for (int i = 0; i < 2; i++)
        #pragma unroll
        for (int j = 0; j < 4; j++)
            wmma::load_matrix_sync(acc[i][j], &Bias[0][warp_n * 64 + j * 16], LDB,
                                   wmma::mem_row_major);

    // per-thread tile-load coordinates
    const int a_row = tid >> 3;             // 0..31 base (4 iters of +? no: slot based)
    // prefetch registers
    float4 pa[4], pb[4];

    // helper lambdas (inlined manually via macros not needed; use functions)
    auto load_tiles = [&](int kt, float4* va, float4* vb) {
        // A tile [128 x 32]: 1024 float4 slots, 4 per thread
        #pragma unroll
        for (int it = 0; it < 4; it++) {
            int slot = tid + it * 256;
            int row = slot >> 3;             // 0..127
            int c4  = (slot & 7) * 4;        // 0..28
            int gr = m0 + row;
            int k = kt * BK + c4;
            float4 v = make_float4(0.f, 0.f, 0.f, 0.f);
            if (gr < NN) {
                const float* src = (k < 128) ? &g_agg[(size_t)gr * D + k]
                                             : &x[(size_t)gr * D + (k - 128)];
                v = *(const float4*)src;
            }
            va[it] = v;
        }
        // B tile [32 x 128]: 1024 float4 slots, 4 per thread
        #pragma unroll
        for (int it = 0; it < 4; it++) {
            int slot = tid + it * 256;
            int row = slot >> 5;             // 0..31
            int c4  = (slot & 31) * 4;       // 0..124
            int k = kt * BK + row;
            const float* src = (k < 128) ? &wl[(size_t)k * D + c4]
                                         : &wr[(size_t)(k - 128) * D + c4];
            vb[it] = *(const float4*)src;
        }
    };

    auto store_tiles = [&](const float4* va, const float4* vb) {
        #pragma unroll
        for (int it = 0; it < 4; it++) {
            int slot = tid + it * 256;
            int row = slot >> 3;
            int c4  = (slot & 7) * 4;
            float4 v = va[it];
            As[row][c4 + 0] = wmma::__float_to_tf32(v.x);
            As[row][c4 + 1] = wmma::__float_to_tf32(v.y);
            As[row][c4 + 2] = wmma::__float_to_tf32(v.z);
            As[row][c4 + 3] = wmma::__float_to_tf32(v.w);
        }
        #pragma unroll
        for (int it = 0; it < 4; it++) {
            int slot = tid + it * 256;
            int row = slot >> 5;
            int c4  = (slot & 31) * 4;
            float4 v = vb[it];
            Bs[row][c4 + 0] = wmma::__float_to_tf32(v.x);
            Bs[row][c4 + 1] = wmma::__float_to_tf32(v.y);
            Bs[row][c4 + 2] = wmma::__float_to_tf32(v.z);
            Bs[row][c4 + 3] = wmma::__float_to_tf32(v.w);
        }
    };

    load_tiles(0, pa, pb);

    for (int kt = 0; kt < 8; kt++) {
        store_tiles(pa, pb);
        __syncthreads();
        if (kt < 7) load_tiles(kt + 1, pa, pb);

        #pragma unroll
        for (int kf = 0; kf < BK / 8; kf++) {
            wmma::fragment<wmma::matrix_a, 16, 16, 8, wmma::precision::tf32, wmma::row_major> af[2];
            #pragma unroll
            for (int i = 0; i < 2; i++)
                wmma::load_matrix_sync(af[i], &As[warp_m * 32 + i * 16][kf * 8], LDA);
            #pragma unroll
            for (int j = 0; j < 4; j++) {
                wmma::fragment<wmma::matrix_b, 16, 16, 8, wmma::precision::tf32, wmma::row_major> bf;
                wmma::load_matrix_sync(bf, &Bs[kf * 8][warp_n * 64 + j * 16], LDB);
                #pragma unroll
                for (int i = 0; i < 2; i++)
                    wmma::mma_sync(acc[i][j], af[i], bf, acc[i][j]);
            }
        }
        __syncthreads();
    }

    // epilogue: NN % 16 == 0 -> tiles fully in or fully out
    #pragma unroll
    for (int i = 0; i < 2; i++) {
        int row0 = m0 + warp_m * 32 + i * 16;
        if (row0 >= NN) continue;
        #pragma unroll
        for (int j = 0; j < 4; j++) {
            int col0 = warp_n * 64 + j * 16;
            wmma::store_matrix_sync(&out[(size_t)row0 * D + col0], acc[i][j], D,
                                    wmma::mem_row_major);
        }
    }
}

// ---------------- launch ----------------
extern "C" void kernel_launch(void* const* d_in, const int* in_sizes, int n_in,
                              void* d_out, int out_size)
{
    const float* x    = (const float*)d_in[0];
    const int*   esrc = (const int*)  d_in[1];
    const int*   edst = (const int*)  d_in[2];
    const float* ew   = (const float*)d_in[3];
    const float* wl   = (const float*)d_in[4];
    const float* bl   = (const float*)d_in[5];
    const float* wr   = (const float*)d_in[6];
    const float* br   = (const float*)d_in[7];
    float* out = (float*)d_out;

    zero_kernel<<<(NN + 255) / 256, 256>>>();
    scatter_kernel<<<(NE + 255) / 256, 256>>>(esrc, edst, ew);
    gather_kernel<<<(NN + 7) / 8, 256>>>(x);
    gemm_kernel<<<(NN + BM - 1) / BM, 256>>>(x, wl, bl, wr, br, out);
}

// round 5
// speedup vs baseline: 1.4247x; 1.0004x over previous
#include <cuda_runtime.h>
#include <mma.h>
#include <cstdint>

using namespace nvcuda;

#define NN 100000
#define NE 600000
#define D  128
#define CAP 64

// ---------------- device scratch ----------------
__device__ int   g_cnt[NN];
__device__ uint2 g_bucket[(size_t)NN * CAP];   // (src, weight_bits)
__device__ float g_agg[(size_t)NN * D];        // tf32-rounded segment_sum(w * x[src])
__device__ float g_xr[(size_t)NN * D];         // tf32-rounded x
__device__ float g_wt[2 * D * D];              // tf32-rounded [Wl ; Wr]

__device__ __forceinline__ float tf32r(float v) { return wmma::__float_to_tf32(v); }

// ---------------- cp.async helpers ----------------
__device__ __forceinline__ void cp_async16(uint32_t dst, const void* src, uint32_t bytes) {
    asm volatile("cp.async.cg.shared.global [%0], [%1], 16, %2;"
                 :: "r"(dst), "l"(src), "r"(bytes) : "memory");
}
#define CP_COMMIT() asm volatile("cp.async.commit_group;" ::: "memory")
#define CP_WAIT(n)  asm volatile("cp.async.wait_group %0;" :: "n"(n) : "memory")

// ---------------- phase 0: zero counters + round weights ----------------
__global__ void __launch_bounds__(256) prep_small_kernel(
    const float* __restrict__ wl, const float* __restrict__ wr)
{
    int i = blockIdx.x * 256 + threadIdx.x;
    if (i < NN) g_cnt[i] = 0;
    if (i < D * D) {
        g_wt[i]         = tf32r(wl[i]);
        g_wt[D * D + i] = tf32r(wr[i]);
    }
}

// ---------------- phase 0b: round x ----------------
__global__ void __launch_bounds__(256) round_x_kernel(const float* __restrict__ x)
{
    size_t i = (size_t)(blockIdx.x * 256 + threadIdx.x) * 4;
    if (i >= (size_t)NN * D) return;
    float4 v = *(const float4*)&x[i];
    v.x = tf32r(v.x); v.y = tf32r(v.y); v.z = tf32r(v.z); v.w = tf32r(v.w);
    *(float4*)&g_xr[i] = v;
}

// ---------------- phase 1: scatter edges into buckets ----------------
__global__ void __launch_bounds__(256) scatter_kernel(
    const int* __restrict__ esrc,
    const int* __restrict__ edst,
    const float* __restrict__ ew)
{
    int e = blockIdx.x * 256 + threadIdx.x;
    if (e >= NE) return;
    int s = __ldg(&esrc[e]);
    int d = __ldg(&edst[e]);
    float w = __ldg(&ew[e]);
    int pos = atomicAdd(&g_cnt[d], 1);
    g_bucket[(size_t)d * CAP + pos] = make_uint2((unsigned)s, __float_as_uint(w));
}

// ---------------- phase 2: gather aggregate (warp per node) ----------------
__global__ void __launch_bounds__(256) gather_kernel(const float* __restrict__ x)
{
    int n = blockIdx.x * 8 + (threadIdx.x >> 5);
    if (n >= NN) return;
    int lane = threadIdx.x & 31;

    int deg = g_cnt[n];
    float4 acc = make_float4(0.f, 0.f, 0.f, 0.f);
    const uint2* bk = &g_bucket[(size_t)n * CAP];
    for (int i = 0; i < deg; i++) {
        uint2 ent = __ldg(&bk[i]);
        float w = __uint_as_float(ent.y);
        float4 v = *(const float4*)&x[(size_t)ent.x * D + lane * 4];
        acc.x += w * v.x; acc.y += w * v.y; acc.z += w * v.z; acc.w += w * v.w;
    }
    acc.x = tf32r(acc.x); acc.y = tf32r(acc.y); acc.z = tf32r(acc.z); acc.w = tf32r(acc.w);
    *(float4*)&g_agg[(size_t)n * D + lane * 4] = acc;
}

// ---------------- phase 3: fused GEMM  out = [agg|x_r] @ [Wl;Wr] + (bl+br) ----------------
#define BM 128
#define BK 16
#define KTOT 256
#define NSTAGE (KTOT / BK)   // 16
#define LDA 20
#define LDB 136

__global__ void __launch_bounds__(256, 2) gemm_kernel(
    const float* __restrict__ bl,
    const float* __restrict__ br,
    float* __restrict__ out)
{
    __shared__ __align__(16) float As[2][BM][LDA];   // 20480 B
    __shared__ __align__(16) float Bs[2][BK][LDB];   // 17408 B
    __shared__ __align__(16) float Bias[16][LDB];    //  8704 B

    const int tid = threadIdx.x;
    const int wid = tid >> 5;
    const int warp_m = wid & 3;       // 0..3 -> 32-row group
    const int warp_n = wid >> 2;      // 0..1 -> 64-col group
    const int m0 = blockIdx.x * BM;

    // bias replica tile
    for (int s = tid; s < 16 * LDB; s += 256) {
        int c = s % LDB;
        (&Bias[0][0])[s] = (c < 128) ? (bl[c] + br[c]) : 0.f;
    }

    // per-thread load coords (2 chunks for A, 2 for B per stage)
    const int a_row0 = tid >> 2;            // slot it=0: row 0..63
    const int a_c4   = (tid & 3) * 4;       // 0,4,8,12
    const int b_row0 = tid >> 5;            // slot it=0: row 0..7
    const int b_c4   = (tid & 31) * 4;      // 0..124

    uint32_t as_base = (uint32_t)__cvta_generic_to_shared(&As[0][0][0]);
    uint32_t bs_base = (uint32_t)__cvta_generic_to_shared(&Bs[0][0][0]);

    auto issue_stage = [&](int kt) {
        int buf = kt & 1;
        // A: [128 x 16] fp32 = 512 x 16B, 2 per thread
        #pragma unroll
        for (int it = 0; it < 2; it++) {
            int row = a_row0 + it * 64;
            int gr  = m0 + row;
            int k   = kt * BK + a_c4;
            const float* src;
            uint32_t bytes = 16;
            if (gr < NN) {
                src = (k < 128) ? &g_agg[(size_t)gr * D + k]
                                : &g_xr[(size_t)gr * D + (k - 128)];
            } else { src = &g_agg[0]; bytes = 0; }
            uint32_t dst = as_base + (buf * BM * LDA + row * LDA + a_c4) * 4;
            cp_async16(dst, src, bytes);
        }
        // B: [16 x 128] fp32 = 512 x 16B, 2 per thread
        #pragma unroll
        for (int it = 0; it < 2; it++) {
            int row = b_row0 + it * 8;
            int k   = kt * BK + row;
            const float* src = &g_wt[(size_t)k * D + b_c4];
            uint32_t dst = bs_base + (buf * BK * LDB + row * LDB + b_c4) * 4;
            cp_async16(dst, src, 16);
        }
        CP_COMMIT();
    };

    issue_stage(0);
    __syncthreads();   // Bias visible

    wmma::fragment<wmma::accumulator, 16, 16, 8, float> acc[2][4];
    #pragma unroll
    for (int i = 0; i < 2; i++)
        #pragma unroll
        for (int j = 0; j < 4; j++)
            wmma::load_matrix_sync(acc[i][j], &Bias[0][warp_n * 64 + j * 16], LDB,
                                   wmma::mem_row_major);

    for (int kt = 0; kt < NSTAGE; kt++) {
        int buf = kt & 1;
        if (kt + 1 < NSTAGE) {
            issue_stage(kt + 1);
            CP_WAIT(1);
        } else {
            CP_WAIT(0);
        }
        __syncthreads();

        #pragma unroll
        for (int kf = 0; kf < BK / 8; kf++) {
            wmma::fragment<wmma::matrix_a, 16, 16, 8, wmma::precision::tf32, wmma::row_major> af[2];
            #pragma unroll
            for (int i = 0; i < 2; i++)
                wmma::load_matrix_sync(af[i], &As[buf][warp_m * 32 + i * 16][kf * 8], LDA);
            #pragma unroll
            for (int j = 0; j < 4; j++) {
                wmma::fragment<wmma::matrix_b, 16, 16, 8, wmma::precision::tf32, wmma::row_major> bf;
                wmma::load_matrix_sync(bf, &Bs[buf][kf * 8][warp_n * 64 + j * 16], LDB);
                #pragma unroll
                for (int i = 0; i < 2; i++)
                    wmma::mma_sync(acc[i][j], af[i], bf, acc[i][j]);
            }
        }
        __syncthreads();   // protect buf before it is refilled in iteration kt+2
    }

    // epilogue: NN % 16 == 0 -> tiles fully in or fully out
    #pragma unroll
    for (int i = 0; i < 2; i++) {
        int row0 = m0 + warp_m * 32 + i * 16;
        if (row0 >= NN) continue;
        #pragma unroll
        for (int j = 0; j < 4; j++) {
            int col0 = warp_n * 64 + j * 16;
            wmma::store_matrix_sync(&out[(size_t)row0 * D + col0], acc[i][j], D,
                                    wmma::mem_row_major);
        }
    }
}

// ---------------- launch ----------------
extern "C" void kernel_launch(void* const* d_in, const int* in_sizes, int n_in,
                              void* d_out, int out_size)
{
    const float* x    = (const float*)d_in[0];
    const int*   esrc = (const int*)  d_in[1];
    const int*   edst = (const int*)  d_in[2];
    const float* ew   = (const float*)d_in[3];
    const float* wl   = (const float*)d_in[4];
    const float* bl   = (const float*)d_in[5];
    const float* wr   = (const float*)d_in[6];
    const float* br   = (const float*)d_in[7];
    float* out = (float*)d_out;

    prep_small_kernel<<<(NN + 255) / 256, 256>>>(wl, wr);
    round_x_kernel<<<(NN * D / 4 + 255) / 256, 256>>>(x);
    scatter_kernel<<<(NE + 255) / 256, 256>>>(esrc, edst, ew);
    gather_kernel<<<(NN + 7) / 8, 256>>>(x);
    gemm_kernel<<<(NN + BM - 1) / BM, 256>>>(bl, br, out);
}

// round 6
// speedup vs baseline: 1.4285x; 1.0027x over previous
#include <cuda_runtime.h>
#include <mma.h>
#include <cstdint>

using namespace nvcuda;

#define NN 100000
#define NE 600000
#define D  128
#define CAP 64

// ---------------- device scratch ----------------
__device__ int   g_cnt[NN];
__device__ uint2 g_bucket[(size_t)NN * CAP];   // (src, weight_bits)
__device__ float g_wt[2 * D * D];              // tf32-rounded [Wl ; Wr]

__device__ __forceinline__ float tf32r(float v) { return wmma::__float_to_tf32(v); }

// ---------------- cp.async helpers ----------------
__device__ __forceinline__ void cp_async16(uint32_t dst, const void* src) {
    asm volatile("cp.async.cg.shared.global [%0], [%1], 16;"
                 :: "r"(dst), "l"(src) : "memory");
}
#define CP_COMMIT() asm volatile("cp.async.commit_group;" ::: "memory")
#define CP_WAIT(n)  asm volatile("cp.async.wait_group %0;" :: "n"(n) : "memory")

// ---------------- prep: zero counters + round weights ----------------
__global__ void __launch_bounds__(256) prep_kernel(
    const float* __restrict__ wl, const float* __restrict__ wr)
{
    int i = blockIdx.x * 256 + threadIdx.x;
    if (i < NN) g_cnt[i] = 0;
    if (i < D * D) {
        g_wt[i]         = tf32r(wl[i]);
        g_wt[D * D + i] = tf32r(wr[i]);
    }
}

// ---------------- scatter edges into buckets ----------------
__global__ void __launch_bounds__(256) scatter_kernel(
    const int* __restrict__ esrc,
    const int* __restrict__ edst,
    const float* __restrict__ ew)
{
    int e = blockIdx.x * 256 + threadIdx.x;
    if (e >= NE) return;
    int s = __ldg(&esrc[e]);
    int d = __ldg(&edst[e]);
    float w = __ldg(&ew[e]);
    int pos = atomicAdd(&g_cnt[d], 1);
    g_bucket[(size_t)d * CAP + pos] = make_uint2((unsigned)s, __float_as_uint(w));
}

// ---------------- fused gather + dual GEMM ----------------
// out[tile] = agg(tile) @ Wl + x(tile) @ Wr + (bl+br)
#define BM 128
#define LDA 132
#define LDB 136

// smem float offsets
#define OFF_AS   0
#define OFF_BS   (BM * LDA)                    // 16896
#define OFF_BIAS (OFF_BS + 2 * 16 * LDB)       // +4352 = 21248
#define SM_FLOATS (OFF_BIAS + 16 * LDB)        // +2176 = 23424  (93696 B)

__global__ void __launch_bounds__(256, 2) fused_kernel(
    const float* __restrict__ x,
    const float* __restrict__ bl,
    const float* __restrict__ br,
    float* __restrict__ out)
{
    extern __shared__ float sm[];
    float (*As)[LDA] = (float(*)[LDA])(sm + OFF_AS);
    float* Bs   = sm + OFF_BS;     // [2][16][LDB]
    float* Bias = sm + OFF_BIAS;   // [16][LDB]

    const int tid = threadIdx.x;
    const int wid = tid >> 5;
    const int lane = tid & 31;
    const int warp_m = wid & 3;    // 32-row group
    const int warp_n = wid >> 2;   // 64-col group
    const int m0 = blockIdx.x * BM;

    // ---- bias replica tile ----
    for (int s = tid; s < 16 * LDB; s += 256) {
        int c = s % LDB;
        Bias[s] = (c < 128) ? (bl[c] + br[c]) : 0.f;
    }

    // ---- phase 1: gather agg rows into As (tf32-rounded) ----
    {
        int node_row = wid * 16;
        for (int i = 0; i < 16; i++) {
            int row = node_row + i;
            int n = m0 + row;
            float4 a = make_float4(0.f, 0.f, 0.f, 0.f);
            if (n < NN) {
                int deg = __ldg(&g_cnt[n]);
                const uint2* bk = &g_bucket[(size_t)n * CAP];
                for (int j = 0; j < deg; j++) {
                    uint2 ent = __ldg(&bk[j]);
                    float w = __uint_as_float(ent.y);
                    float4 v = *(const float4*)&x[(size_t)ent.x * D + lane * 4];
                    a.x += w * v.x; a.y += w * v.y; a.z += w * v.z; a.w += w * v.w;
                }
            }
            a.x = tf32r(a.x); a.y = tf32r(a.y); a.z = tf32r(a.z); a.w = tf32r(a.w);
            *(float4*)&As[row][lane * 4] = a;
        }
    }
    __syncthreads();

    // ---- init accumulators from bias ----
    wmma::fragment<wmma::accumulator, 16, 16, 8, float> acc[2][4];
    #pragma unroll
    for (int i = 0; i < 2; i++)
        #pragma unroll
        for (int j = 0; j < 4; j++)
            wmma::load_matrix_sync(acc[i][j], &Bias[warp_n * 64 + j * 16], LDB,
                                   wmma::mem_row_major);

    // ---- B-chunk loader: chunk = [16 x 128] of g_wt starting at k-row ----
    uint32_t bs_base = (uint32_t)__cvta_generic_to_shared(Bs);
    const int b_row = tid >> 5;          // 0..7 (+8 second slot)
    const int b_c4  = (tid & 31) * 4;
    auto issue_b = [&](int kglob, int buf) {
        #pragma unroll
        for (int it = 0; it < 2; it++) {
            int row = b_row + it * 8;
            const float* src = &g_wt[(size_t)(kglob + row) * D + b_c4];
            uint32_t dst = bs_base + (buf * 16 * LDB + row * LDB + b_c4) * 4;
            cp_async16(dst, src);
        }
        CP_COMMIT();
    };

    // ---- GEMM over one K-half (As holds 128 k-columns; weights at kbase) ----
    auto gemm_half = [&](int kbase) {
        issue_b(kbase, 0);
        for (int kc = 0; kc < 8; kc++) {
            int buf = kc & 1;
            if (kc < 7) { issue_b(kbase + (kc + 1) * 16, buf ^ 1); CP_WAIT(1); }
            else        { CP_WAIT(0); }
            __syncthreads();
            #pragma unroll
            for (int kf = 0; kf < 2; kf++) {
                wmma::fragment<wmma::matrix_a, 16, 16, 8, wmma::precision::tf32,
                               wmma::row_major> af[2];
                #pragma unroll
                for (int i = 0; i < 2; i++)
                    wmma::load_matrix_sync(af[i],
                        &As[warp_m * 32 + i * 16][kc * 16 + kf * 8], LDA);
                #pragma unroll
                for (int j = 0; j < 4; j++) {
                    wmma::fragment<wmma::matrix_b, 16, 16, 8, wmma::precision::tf32,
                                   wmma::row_major> bf;
                    wmma::load_matrix_sync(bf,
                        &Bs[buf * 16 * LDB + kf * 8 * LDB + warp_n * 64 + j * 16], LDB);
                    #pragma unroll
                    for (int i = 0; i < 2; i++)
                        wmma::mma_sync(acc[i][j], af[i], bf, acc[i][j]);
                }
            }
            __syncthreads();
        }
    };

    // ---- phase 2: agg @ Wl ----
    gemm_half(0);

    // ---- phase 3: overwrite As with this CTA's x rows (tf32-rounded) ----
    __syncthreads();
    #pragma unroll
    for (int it = 0; it < 16; it++) {
        int slot = tid + it * 256;        // 0..4095
        int row = slot >> 5;              // 0..127
        int c4  = (slot & 31) * 4;
        int gr = m0 + row;
        float4 v = make_float4(0.f, 0.f, 0.f, 0.f);
        if (gr < NN) v = *(const float4*)&x[(size_t)gr * D + c4];
        v.x = tf32r(v.x); v.y = tf32r(v.y); v.z = tf32r(v.z); v.w = tf32r(v.w);
        *(float4*)&As[row][c4] = v;
    }
    __syncthreads();

    // ---- phase 4: x @ Wr ----
    gemm_half(128);

    // ---- epilogue (NN % 16 == 0 -> tiles fully in or out) ----
    #pragma unroll
    for (int i = 0; i < 2; i++) {
        int row0 = m0 + warp_m * 32 + i * 16;
        if (row0 >= NN) continue;
        #pragma unroll
        for (int j = 0; j < 4; j++) {
            int col0 = warp_n * 64 + j * 16;
            wmma::store_matrix_sync(&out[(size_t)row0 * D + col0], acc[i][j], D,
                                    wmma::mem_row_major);
        }
    }
}

// ---------------- launch ----------------
extern "C" void kernel_launch(void* const* d_in, const int* in_sizes, int n_in,
                              void* d_out, int out_size)
{
    const float* x    = (const float*)d_in[0];
    const int*   esrc = (const int*)  d_in[1];
    const int*   edst = (const int*)  d_in[2];
    const float* ew   = (const float*)d_in[3];
    const float* wl   = (const float*)d_in[4];
    const float* bl   = (const float*)d_in[5];
    const float* wr   = (const float*)d_in[6];
    const float* br   = (const float*)d_in[7];
    float* out = (float*)d_out;

    static bool attr_set = false;
    if (!attr_set) {
        cudaFuncSetAttribute(fused_kernel,
                             cudaFuncAttributeMaxDynamicSharedMemorySize,
                             SM_FLOATS * 4);
        attr_set = true;
    }

    prep_kernel<<<(NN + 255) / 256, 256>>>(wl, wr);
    scatter_kernel<<<(NE + 255) / 256, 256>>>(esrc, edst, ew);
    fused_kernel<<<(NN + BM - 1) / BM, 256, SM_FLOATS * 4>>>(x, bl, br, out);
}

// round 7
// speedup vs baseline: 2.0196x; 1.4138x over previous
#include <cuda_runtime.h>
#include <cuda_fp16.h>
#include <mma.h>
#include <cstdint>

using namespace nvcuda;

#define NN 100000
#define NE 600000
#define D  128
#define CAP 64

// ---------------- device scratch ----------------
__device__ int    g_cnt[NN];
__device__ uint2  g_bucket[(size_t)NN * CAP];   // (src, weight_bits)
__device__ __half g_wt[2 * D * D];              // fp16 [Wl ; Wr]  (K-row major [256][128])

// ---------------- cp.async helpers ----------------
__device__ __forceinline__ void cp_async16(uint32_t dst, const void* src) {
    asm volatile("cp.async.cg.shared.global [%0], [%1], 16;"
                 :: "r"(dst), "l"(src) : "memory");
}
#define CP_COMMIT() asm volatile("cp.async.commit_group;" ::: "memory")
#define CP_WAIT(n)  asm volatile("cp.async.wait_group %0;" :: "n"(n) : "memory")

// ---------------- prep: zero counters + convert weights to fp16 ----------------
__global__ void __launch_bounds__(256) prep_kernel(
    const float* __restrict__ wl, const float* __restrict__ wr)
{
    int i = blockIdx.x * 256 + threadIdx.x;
    if (i < NN) g_cnt[i] = 0;
    if (i < D * D) {
        g_wt[i]         = __float2half_rn(wl[i]);
        g_wt[D * D + i] = __float2half_rn(wr[i]);
    }
}

// ---------------- scatter edges into buckets ----------------
__global__ void __launch_bounds__(256) scatter_kernel(
    const int* __restrict__ esrc,
    const int* __restrict__ edst,
    const float* __restrict__ ew)
{
    int e = blockIdx.x * 256 + threadIdx.x;
    if (e >= NE) return;
    int s = __ldg(&esrc[e]);
    int d = __ldg(&edst[e]);
    float w = __ldg(&ew[e]);
    int pos = atomicAdd(&g_cnt[d], 1);
    g_bucket[(size_t)d * CAP + pos] = make_uint2((unsigned)s, __float_as_uint(w));
}

// ---------------- fused gather + dual fp16 GEMM ----------------
// out[tile] = agg(tile) @ Wl + x(tile) @ Wr + (bl+br)
#define BM 128
#define LDA 136     // halves (272 B rows, 16B aligned)
#define LDB 136     // halves
#define LDBI 136    // floats (bias tile)

// smem byte offsets
#define OFF_AS   0
#define OFF_BS   (BM * LDA * 2)                      // 34816
#define OFF_BIAS (OFF_BS + 2 * 16 * LDB * 2)         // +8704 = 43520
#define SM_BYTES (OFF_BIAS + 16 * LDBI * 4)          // +8704 = 52224

__global__ void __launch_bounds__(256, 2) fused_kernel(
    const float* __restrict__ x,
    const float* __restrict__ bl,
    const float* __restrict__ br,
    float* __restrict__ out)
{
    extern __shared__ char smraw[];
    __half (*As)[LDA] = (__half(*)[LDA])(smraw + OFF_AS);
    __half* Bs   = (__half*)(smraw + OFF_BS);    // [2][16][LDB]
    float*  Bias = (float*) (smraw + OFF_BIAS);  // [16][LDBI]

    const int tid = threadIdx.x;
    const int wid = tid >> 5;
    const int lane = tid & 31;
    const int warp_m = wid & 3;    // 32-row group
    const int warp_n = wid >> 2;   // 64-col group
    const int m0 = blockIdx.x * BM;

    // ---- bias replica tile (fp32) ----
    for (int s = tid; s < 16 * LDBI; s += 256) {
        int c = s % LDBI;
        Bias[s] = (c < 128) ? (bl[c] + br[c]) : 0.f;
    }

    // ---- phase 1: gather agg rows into As (fp32 accumulate -> fp16) ----
    {
        int node_row = wid * 16;
        for (int i = 0; i < 16; i++) {
            int row = node_row + i;
            int n = m0 + row;
            float4 a = make_float4(0.f, 0.f, 0.f, 0.f);
            if (n < NN) {
                int deg = __ldg(&g_cnt[n]);
                const uint2* bk = &g_bucket[(size_t)n * CAP];
                for (int j = 0; j < deg; j++) {
                    uint2 ent = __ldg(&bk[j]);
                    float w = __uint_as_float(ent.y);
                    float4 v = *(const float4*)&x[(size_t)ent.x * D + lane * 4];
                    a.x += w * v.x; a.y += w * v.y; a.z += w * v.z; a.w += w * v.w;
                }
            }
            __half2* dst = (__half2*)&As[row][lane * 4];
            dst[0] = __floats2half2_rn(a.x, a.y);
            dst[1] = __floats2half2_rn(a.z, a.w);
        }
    }
    __syncthreads();

    // ---- init accumulators from bias ----
    wmma::fragment<wmma::accumulator, 16, 16, 16, float> acc[2][4];
    #pragma unroll
    for (int i = 0; i < 2; i++)
        #pragma unroll
        for (int j = 0; j < 4; j++)
            wmma::load_matrix_sync(acc[i][j], &Bias[warp_n * 64 + j * 16], LDBI,
                                   wmma::mem_row_major);

    // ---- B chunk loader: [16 k-rows x 128 cols] fp16 = 4KB, 1 cp per thread ----
    uint32_t bs_base = (uint32_t)__cvta_generic_to_shared(Bs);
    const int b_row = tid >> 4;          // 0..15
    const int b_c8  = (tid & 15) * 8;    // halves, 0..120
    auto issue_b = [&](int kglob, int buf) {
        const __half* src = &g_wt[(size_t)(kglob + b_row) * D + b_c8];
        uint32_t dst = bs_base + (buf * 16 * LDB + b_row * LDB + b_c8) * 2;
        cp_async16(dst, src);
        CP_COMMIT();
    };

    // ---- GEMM over one K-half (As holds 128 k-cols; weights rows at kbase) ----
    auto gemm_half = [&](int kbase) {
        issue_b(kbase, 0);
        for (int kc = 0; kc < 8; kc++) {
            int buf = kc & 1;
            if (kc < 7) { issue_b(kbase + (kc + 1) * 16, buf ^ 1); CP_WAIT(1); }
            else        { CP_WAIT(0); }
            __syncthreads();

            wmma::fragment<wmma::matrix_a, 16, 16, 16, __half, wmma::row_major> af[2];
            #pragma unroll
            for (int i = 0; i < 2; i++)
                wmma::load_matrix_sync(af[i], &As[warp_m * 32 + i * 16][kc * 16], LDA);
            #pragma unroll
            for (int j = 0; j < 4; j++) {
                wmma::fragment<wmma::matrix_b, 16, 16, 16, __half, wmma::row_major> bf;
                wmma::load_matrix_sync(bf, &Bs[buf * 16 * LDB + warp_n * 64 + j * 16], LDB);
                #pragma unroll
                for (int i = 0; i < 2; i++)
                    wmma::mma_sync(acc[i][j], af[i], bf, acc[i][j]);
            }
            __syncthreads();
        }
    };

    // ---- phase 2: agg @ Wl ----
    gemm_half(0);

    // ---- phase 3: overwrite As with this CTA's x rows (fp16) ----
    __syncthreads();
    #pragma unroll
    for (int it = 0; it < 8; it++) {
        int slot = tid + it * 256;        // 0..2047
        int row = slot >> 4;              // 0..127
        int c8  = (slot & 15) * 8;        // 0..120
        int gr = m0 + row;
        float4 v0 = make_float4(0.f, 0.f, 0.f, 0.f), v1 = v0;
        if (gr < NN) {
            v0 = *(const float4*)&x[(size_t)gr * D + c8];
            v1 = *(const float4*)&x[(size_t)gr * D + c8 + 4];
        }
        __half2 h[4];
        h[0] = __floats2half2_rn(v0.x, v0.y);
        h[1] = __floats2half2_rn(v0.z, v0.w);
        h[2] = __floats2half2_rn(v1.x, v1.y);
        h[3] = __floats2half2_rn(v1.z, v1.w);
        *(uint4*)&As[row][c8] = *(uint4*)h;
    }
    __syncthreads();

    // ---- phase 4: x @ Wr ----
    gemm_half(128);

    // ---- epilogue (NN % 16 == 0 -> tiles fully in or out) ----
    #pragma unroll
    for (int i = 0; i < 2; i++) {
        int row0 = m0 + warp_m * 32 + i * 16;
        if (row0 >= NN) continue;
        #pragma unroll
        for (int j = 0; j < 4; j++) {
            int col0 = warp_n * 64 + j * 16;
            wmma::store_matrix_sync(&out[(size_t)row0 * D + col0], acc[i][j], D,
                                    wmma::mem_row_major);
        }
    }
}

// ---------------- launch ----------------
extern "C" void kernel_launch(void* const* d_in, const int* in_sizes, int n_in,
                              void* d_out, int out_size)
{
    const float* x    = (const float*)d_in[0];
    const int*   esrc = (const int*)  d_in[1];
    const int*   edst = (const int*)  d_in[2];
    const float* ew   = (const float*)d_in[3];
    const float* wl   = (const float*)d_in[4];
    const float* bl   = (const float*)d_in[5];
    const float* wr   = (const float*)d_in[6];
    const float* br   = (const float*)d_in[7];
    float* out = (float*)d_out;

    static bool attr_set = false;
    if (!attr_set) {
        cudaFuncSetAttribute(fused_kernel,
                             cudaFuncAttributeMaxDynamicSharedMemorySize, SM_BYTES);
        attr_set = true;
    }

    prep_kernel<<<(NN + 255) / 256, 256>>>(wl, wr);
    scatter_kernel<<<(NE + 255) / 256, 256>>>(esrc, edst, ew);
    fused_kernel<<<(NN + BM - 1) / BM, 256, SM_BYTES>>>(x, bl, br, out);
}

// round 8
// speedup vs baseline: 2.0520x; 1.0161x over previous
#include <cuda_runtime.h>
#include <cuda_fp16.h>
#include <mma.h>
#include <cstdint>

using namespace nvcuda;

#define NN 100000
#define NE 600000
#define D  128
#define CAP 64

// ---------------- device scratch ----------------
__device__ int    g_cnt[NN];
__device__ uint2  g_bucket[(size_t)NN * CAP];   // (src, weight_bits)
__device__ __half g_wt[2 * D * D];              // fp16 [Wl ; Wr]  (K-row major [256][128])

// ---------------- cp.async helpers ----------------
__device__ __forceinline__ void cp_async16(uint32_t dst, const void* src) {
    asm volatile("cp.async.cg.shared.global [%0], [%1], 16;"
                 :: "r"(dst), "l"(src) : "memory");
}
#define CP_COMMIT() asm volatile("cp.async.commit_group;" ::: "memory")
#define CP_WAIT(n)  asm volatile("cp.async.wait_group %0;" :: "n"(n) : "memory")

// ---------------- prep: zero counters + convert weights to fp16 ----------------
__global__ void __launch_bounds__(256) prep_kernel(
    const float* __restrict__ wl, const float* __restrict__ wr)
{
    int i = blockIdx.x * 256 + threadIdx.x;
    if (i < NN) g_cnt[i] = 0;
    if (i < D * D) {
        g_wt[i]         = __float2half_rn(wl[i]);
        g_wt[D * D + i] = __float2half_rn(wr[i]);
    }
}

// ---------------- scatter edges into buckets ----------------
__global__ void __launch_bounds__(256) scatter_kernel(
    const int* __restrict__ esrc,
    const int* __restrict__ edst,
    const float* __restrict__ ew)
{
    int e = blockIdx.x * 256 + threadIdx.x;
    if (e >= NE) return;
    int s = __ldg(&esrc[e]);
    int d = __ldg(&edst[e]);
    float w = __ldg(&ew[e]);
    int pos = atomicAdd(&g_cnt[d], 1);
    g_bucket[(size_t)d * CAP + pos] = make_uint2((unsigned)s, __float_as_uint(w));
}

// ---------------- fused gather + dual fp16 GEMM (B fully smem-resident) -------
// out[tile] = agg(tile) @ Wl + x(tile) @ Wr + (bl+br)
#define BM 128
#define LDA 136     // halves
#define LDB 136     // halves
#define LDBI 136    // floats

// smem byte offsets
#define OFF_AS   0
#define OFF_B    (BM * LDA * 2)                      // 34816
#define OFF_BIAS (OFF_B + 256 * LDB * 2)             // +69632 = 104448
#define SM_BYTES (OFF_BIAS + 16 * LDBI * 4)          // +8704  = 113152

__global__ void __launch_bounds__(256, 2) fused_kernel(
    const float* __restrict__ x,
    const float* __restrict__ bl,
    const float* __restrict__ br,
    float* __restrict__ out)
{
    extern __shared__ char smraw[];
    __half (*As)[LDA] = (__half(*)[LDA])(smraw + OFF_AS);
    __half* Bsm  = (__half*)(smraw + OFF_B);     // [256][LDB]
    float*  Bias = (float*) (smraw + OFF_BIAS);  // [16][LDBI]

    const int tid = threadIdx.x;
    const int wid = tid >> 5;
    const int lane = tid & 31;
    const int warp_m = wid & 3;    // 32-row group
    const int warp_n = wid >> 2;   // 64-col group
    const int m0 = blockIdx.x * BM;

    // ---- issue the ENTIRE B load now (64KB, 16 cp per thread); gather hides it ----
    {
        uint32_t b_base = (uint32_t)__cvta_generic_to_shared(Bsm);
        const int c8 = (tid & 15) * 8;        // halves 0..120
        const int r0 = tid >> 4;              // 0..15
        #pragma unroll
        for (int it = 0; it < 16; it++) {
            int row = r0 + it * 16;           // 0..255
            cp_async16(b_base + (row * LDB + c8) * 2,
                       &g_wt[(size_t)row * D + c8]);
        }
        CP_COMMIT();
    }

    // ---- bias replica tile (fp32) ----
    for (int s = tid; s < 16 * LDBI; s += 256) {
        int c = s % LDBI;
        Bias[s] = (c < 128) ? (bl[c] + br[c]) : 0.f;
    }

    // ---- phase 1: gather agg rows into As (fp32 accumulate -> fp16) ----
    {
        int node_row = wid * 16;
        for (int i = 0; i < 16; i++) {
            int row = node_row + i;
            int n = m0 + row;
            float4 a = make_float4(0.f, 0.f, 0.f, 0.f);
            if (n < NN) {
                int deg = __ldg(&g_cnt[n]);
                const uint2* bk = &g_bucket[(size_t)n * CAP];
                for (int j = 0; j < deg; j++) {
                    uint2 ent = __ldg(&bk[j]);
                    float w = __uint_as_float(ent.y);
                    float4 v = *(const float4*)&x[(size_t)ent.x * D + lane * 4];
                    a.x += w * v.x; a.y += w * v.y; a.z += w * v.z; a.w += w * v.w;
                }
            }
            __half2* dst = (__half2*)&As[row][lane * 4];
            dst[0] = __floats2half2_rn(a.x, a.y);
            dst[1] = __floats2half2_rn(a.z, a.w);
        }
    }
    CP_WAIT(0);          // B resident
    __syncthreads();     // As + B + Bias visible

    // ---- init accumulators from bias ----
    wmma::fragment<wmma::accumulator, 16, 16, 16, float> acc[2][4];
    #pragma unroll
    for (int i = 0; i < 2; i++)
        #pragma unroll
        for (int j = 0; j < 4; j++)
            wmma::load_matrix_sync(acc[i][j], &Bias[warp_n * 64 + j * 16], LDBI,
                                   wmma::mem_row_major);

    // ---- GEMM over one K-half: NO barriers, NO waits inside ----
    auto gemm_half = [&](int kbase) {
        #pragma unroll
        for (int kc = 0; kc < 8; kc++) {
            wmma::fragment<wmma::matrix_a, 16, 16, 16, __half, wmma::row_major> af[2];
            #pragma unroll
            for (int i = 0; i < 2; i++)
                wmma::load_matrix_sync(af[i], &As[warp_m * 32 + i * 16][kc * 16], LDA);
            #pragma unroll
            for (int j = 0; j < 4; j++) {
                wmma::fragment<wmma::matrix_b, 16, 16, 16, __half, wmma::row_major> bf;
                wmma::load_matrix_sync(bf,
                    &Bsm[(size_t)(kbase + kc * 16) * LDB + warp_n * 64 + j * 16], LDB);
                #pragma unroll
                for (int i = 0; i < 2; i++)
                    wmma::mma_sync(acc[i][j], af[i], bf, acc[i][j]);
            }
        }
    };

    // ---- phase 2: agg @ Wl ----
    gemm_half(0);

    // ---- phase 3: overwrite As with this CTA's x rows (fp16) ----
    __syncthreads();
    #pragma unroll
    for (int it = 0; it < 8; it++) {
        int slot = tid + it * 256;        // 0..2047
        int row = slot >> 4;              // 0..127
        int c8  = (slot & 15) * 8;        // 0..120
        int gr = m0 + row;
        float4 v0 = make_float4(0.f, 0.f, 0.f, 0.f), v1 = v0;
        if (gr < NN) {
            v0 = *(const float4*)&x[(size_t)gr * D + c8];
            v1 = *(const float4*)&x[(size_t)gr * D + c8 + 4];
        }
        __half2 h[4];
        h[0] = __floats2half2_rn(v0.x, v0.y);
        h[1] = __floats2half2_rn(v0.z, v0.w);
        h[2] = __floats2half2_rn(v1.x, v1.y);
        h[3] = __floats2half2_rn(v1.z, v1.w);
        *(uint4*)&As[row][c8] = *(uint4*)h;
    }
    __syncthreads();

    // ---- phase 4: x @ Wr ----
    gemm_half(128);

    // ---- epilogue (NN % 16 == 0 -> tiles fully in or out) ----
    #pragma unroll
    for (int i = 0; i < 2; i++) {
        int row0 = m0 + warp_m * 32 + i * 16;
        if (row0 >= NN) continue;
        #pragma unroll
        for (int j = 0; j < 4; j++) {
            int col0 = warp_n * 64 + j * 16;
            wmma::store_matrix_sync(&out[(size_t)row0 * D + col0], acc[i][j], D,
                                    wmma::mem_row_major);
        }
    }
}

// ---------------- launch ----------------
extern "C" void kernel_launch(void* const* d_in, const int* in_sizes, int n_in,
                              void* d_out, int out_size)
{
    const float* x    = (const float*)d_in[0];
    const int*   esrc = (const int*)  d_in[1];
    const int*   edst = (const int*)  d_in[2];
    const float* ew   = (const float*)d_in[3];
    const float* wl   = (const float*)d_in[4];
    const float* bl   = (const float*)d_in[5];
    const float* wr   = (const float*)d_in[6];
    const float* br   = (const float*)d_in[7];
    float* out = (float*)d_out;

    static bool attr_set = false;
    if (!attr_set) {
        cudaFuncSetAttribute(fused_kernel,
                             cudaFuncAttributeMaxDynamicSharedMemorySize, SM_BYTES);
        attr_set = true;
    }

    prep_kernel<<<(NN + 255) / 256, 256>>>(wl, wr);
    scatter_kernel<<<(NE + 255) / 256, 256>>>(esrc, edst, ew);
    fused_kernel<<<(NN + BM - 1) / BM, 256, SM_BYTES>>>(x, bl, br, out);
}